// round 5
// baseline (speedup 1.0000x reference)
#include <cuda_runtime.h>

// ---------------------------------------------------------------------------
// GraphSAGE on GB300 — fp32, CSR-based mean aggregation + fused dual GEMM.
// Index inputs (x, edge_index) are int32 per harness canonicalization.
//
// Pipeline per call (all graph-capturable, default stream):
//   1. zero_deg, count_deg (int atomics), scan (1 block) -> rowptr/cursor/inv
//   2. fill_csr (int atomics) -> g_col
//   3. gather_emb: h0 = emb[x]
//   4. 3x { aggregate (warp/node, no float atomics) ; gemm_fused<dual,prelu> }
//   5. gemm_fused<single,linear> -> d_out
// ---------------------------------------------------------------------------

#define NMAX 100032
#define EMAX 3200000
#define D    256
#define DV4  64   // D / 4

// Scratch (static device memory; allocation-free at run time)
__device__ float g_bufA[(size_t)NMAX * D];
__device__ float g_bufB[(size_t)NMAX * D];
__device__ float g_agg [(size_t)NMAX * D];
__device__ int   g_deg[NMAX];
__device__ int   g_rowptr[NMAX + 1];
__device__ int   g_cursor[NMAX];
__device__ float g_inv[NMAX];
__device__ int   g_col[EMAX];

__device__ __forceinline__ float* selbuf(int s) {
    return (s == 0) ? g_bufA : (s == 1) ? g_bufB : g_agg;
}

// ---------------------------------------------------------------------------
// CSR construction
// ---------------------------------------------------------------------------
__global__ void zero_deg(int n) {
    int i = blockIdx.x * blockDim.x + threadIdx.x;
    if (i < n) g_deg[i] = 0;
}

__global__ void count_deg(const int* __restrict__ dst, int E) {
    int i = blockIdx.x * blockDim.x + threadIdx.x;
    if (i < E) atomicAdd(&g_deg[dst[i]], 1);
}

// Single-block exclusive scan over g_deg -> rowptr, cursor, inv.
__global__ void scan_kernel(int n, int E) {
    __shared__ int sums[1024];
    int t = threadIdx.x;
    int chunk = (n + 1023) >> 10;
    int b = t * chunk;
    int e = min(b + chunk, n);
    int s = 0;
    for (int i = b; i < e; i++) s += g_deg[i];
    sums[t] = s;
    __syncthreads();
    // Hillis-Steele inclusive scan
    for (int off = 1; off < 1024; off <<= 1) {
        int v = (t >= off) ? sums[t - off] : 0;
        __syncthreads();
        sums[t] += v;
        __syncthreads();
    }
    int prefix = (t == 0) ? 0 : sums[t - 1];
    for (int i = b; i < e; i++) {
        int d = g_deg[i];
        g_rowptr[i] = prefix;
        g_cursor[i] = prefix;
        g_inv[i]    = 1.0f / (float)max(d, 1);
        prefix += d;
    }
    if (t == 0) g_rowptr[n] = E;
}

__global__ void fill_csr(const int* __restrict__ src,
                         const int* __restrict__ dst, int E) {
    int i = blockIdx.x * blockDim.x + threadIdx.x;
    if (i < E) {
        int d = dst[i];
        int p = atomicAdd(&g_cursor[d], 1);
        g_col[p] = src[i];
    }
}

// ---------------------------------------------------------------------------
// h0 = emb[x]   (float4-vectorized gather into g_bufA)
// ---------------------------------------------------------------------------
__global__ void gather_emb(const int* __restrict__ x,
                           const float* __restrict__ emb, int n) {
    int i = blockIdx.x * blockDim.x + threadIdx.x;
    if (i < n * DV4) {
        int node = i >> 6;
        int c    = i & 63;
        ((float4*)g_bufA)[i] =
            ((const float4*)emb)[(size_t)x[node] * DV4 + c];
    }
}

// ---------------------------------------------------------------------------
// Mean aggregation: one warp per node, register accumulation, no atomics.
// Each lane owns 8 consecutive channels (2 float4).
// ---------------------------------------------------------------------------
__device__ __forceinline__ void f4add(float4& a, const float4& v) {
    a.x += v.x; a.y += v.y; a.z += v.z; a.w += v.w;
}

__global__ void __launch_bounds__(256)
aggregate(int selH, int n) {
    int w = (blockIdx.x * blockDim.x + threadIdx.x) >> 5;
    if (w >= n) return;
    int lane = threadIdx.x & 31;
    const float4* hv = (const float4*)selbuf(selH);
    int s = g_rowptr[w];
    int e = g_rowptr[w + 1];
    int base = lane * 2;
    float4 acc0 = make_float4(0.f, 0.f, 0.f, 0.f);
    float4 acc1 = make_float4(0.f, 0.f, 0.f, 0.f);
    for (int t = s; t < e; t++) {
        size_t j = (size_t)g_col[t] * DV4;
        float4 v0 = __ldg(&hv[j + base]);
        float4 v1 = __ldg(&hv[j + base + 1]);
        f4add(acc0, v0);
        f4add(acc1, v1);
    }
    float iv = g_inv[w];
    acc0.x *= iv; acc0.y *= iv; acc0.z *= iv; acc0.w *= iv;
    acc1.x *= iv; acc1.y *= iv; acc1.z *= iv; acc1.w *= iv;
    float4* out = (float4*)g_agg;
    out[(size_t)w * DV4 + base]     = acc0;
    out[(size_t)w * DV4 + base + 1] = acc1;
}

// ---------------------------------------------------------------------------
// Fused dual GEMM:  C = A1 @ W1^T [+ A2 @ W2^T] + bias  [, PReLU]
// A row-major [n, 256], W row-major [256, 256] (out_ch x in_ch).
// Tile 64x64x32, 256 threads, 4x4 register tile per thread.
// Smem stored k-major [BK][BM+pad] so inner loop uses LDS.128.
// ---------------------------------------------------------------------------
template <bool DUAL, bool PRELU>
__global__ void __launch_bounds__(256)
gemm_fused(int selA1, int selA2,
           const float* __restrict__ W1, const float* __restrict__ W2,
           const float* __restrict__ bias, const float* __restrict__ slope,
           float* __restrict__ Cext, int selC, int nrows) {
    constexpr int BM = 64, BN = 64, BK = 32, PADS = 68;
    __shared__ float sA1[BK * PADS];
    __shared__ float sW1[BK * PADS];
    __shared__ float sA2[DUAL ? BK * PADS : 4];
    __shared__ float sW2[DUAL ? BK * PADS : 4];

    const float* A1 = selbuf(selA1);
    const float* A2 = DUAL ? selbuf(selA2) : nullptr;
    float* C = (selC >= 0) ? selbuf(selC) : Cext;

    int tid = threadIdx.x;
    int m0 = blockIdx.x * BM;
    int o0 = blockIdx.y * BN;

    // loader mapping: row within tile, k-subgroup of 8
    int lr = tid >> 2;
    int lk = (tid & 3) * 8;
    int arow = min(m0 + lr, nrows - 1);
    const float* a1g = A1 + (size_t)arow * D + lk;
    const float* a2g = DUAL ? (A2 + (size_t)arow * D + lk) : nullptr;
    const float* w1g = W1 + (size_t)(o0 + lr) * D + lk;
    const float* w2g = DUAL ? (W2 + (size_t)(o0 + lr) * D + lk) : nullptr;

    // compute mapping: 16x16 thread grid of 4x4 tiles
    int tx = tid & 15;
    int ty = tid >> 4;

    float acc[4][4];
#pragma unroll
    for (int i = 0; i < 4; i++)
#pragma unroll
        for (int j = 0; j < 4; j++) acc[i][j] = 0.f;

    for (int kt = 0; kt < D; kt += BK) {
        float4 va0 = *(const float4*)(a1g + kt);
        float4 va1 = *(const float4*)(a1g + kt + 4);
        float4 vw0 = *(const float4*)(w1g + kt);
        float4 vw1 = *(const float4*)(w1g + kt + 4);
        float4 vb0, vb1, vx0, vx1;
        if (DUAL) {
            vb0 = *(const float4*)(a2g + kt);
            vb1 = *(const float4*)(a2g + kt + 4);
            vx0 = *(const float4*)(w2g + kt);
            vx1 = *(const float4*)(w2g + kt + 4);
        }
        __syncthreads();  // previous tile's compute done
#pragma unroll
        for (int u = 0; u < 4; u++) {
            sA1[(lk + u) * PADS + lr]     = ((const float*)&va0)[u];
            sA1[(lk + 4 + u) * PADS + lr] = ((const float*)&va1)[u];
            sW1[(lk + u) * PADS + lr]     = ((const float*)&vw0)[u];
            sW1[(lk + 4 + u) * PADS + lr] = ((const float*)&vw1)[u];
            if (DUAL) {
                sA2[(lk + u) * PADS + lr]     = ((const float*)&vb0)[u];
                sA2[(lk + 4 + u) * PADS + lr] = ((const float*)&vb1)[u];
                sW2[(lk + u) * PADS + lr]     = ((const float*)&vx0)[u];
                sW2[(lk + 4 + u) * PADS + lr] = ((const float*)&vx1)[u];
            }
        }
        __syncthreads();
#pragma unroll
        for (int k = 0; k < BK; k++) {
            float4 a1 = *(const float4*)&sA1[k * PADS + ty * 4];
            float4 w1 = *(const float4*)&sW1[k * PADS + tx * 4];
            float am[4] = {a1.x, a1.y, a1.z, a1.w};
            float wn[4] = {w1.x, w1.y, w1.z, w1.w};
#pragma unroll
            for (int i = 0; i < 4; i++)
#pragma unroll
                for (int j = 0; j < 4; j++) acc[i][j] += am[i] * wn[j];
            if (DUAL) {
                float4 a2 = *(const float4*)&sA2[k * PADS + ty * 4];
                float4 w2 = *(const float4*)&sW2[k * PADS + tx * 4];
                float bm[4] = {a2.x, a2.y, a2.z, a2.w};
                float xn[4] = {w2.x, w2.y, w2.z, w2.w};
#pragma unroll
                for (int i = 0; i < 4; i++)
#pragma unroll
                    for (int j = 0; j < 4; j++) acc[i][j] += bm[i] * xn[j];
            }
        }
    }

    float sl = PRELU ? __ldg(slope) : 0.f;
    float bj[4];
#pragma unroll
    for (int j = 0; j < 4; j++) bj[j] = __ldg(&bias[o0 + tx * 4 + j]);

#pragma unroll
    for (int i = 0; i < 4; i++) {
        int row = m0 + ty * 4 + i;
        if (row < nrows) {
            float4 o;
            o.x = acc[i][0] + bj[0];
            o.y = acc[i][1] + bj[1];
            o.z = acc[i][2] + bj[2];
            o.w = acc[i][3] + bj[3];
            if (PRELU) {
                o.x = (o.x >= 0.f) ? o.x : sl * o.x;
                o.y = (o.y >= 0.f) ? o.y : sl * o.y;
                o.z = (o.z >= 0.f) ? o.z : sl * o.z;
                o.w = (o.w >= 0.f) ? o.w : sl * o.w;
            }
            *(float4*)&C[(size_t)row * D + o0 + tx * 4] = o;
        }
    }
}

// ---------------------------------------------------------------------------
// Host launcher
// Inputs: 0 x(i32,N) 1 edge_index(i32,2E) 2 edge_weight(f32,E,unused) 3 emb
//         4 Wl1 5 bl1 6 Wr1 7 a1  8 Wl2 9 bl2 10 Wr2 11 a2
//         12 Wl3 13 bl3 14 Wr3 15 a3  16 Wout 17 bout
// ---------------------------------------------------------------------------
extern "C" void kernel_launch(void* const* d_in, const int* in_sizes, int n_in,
                              void* d_out, int out_size) {
    const int*   x   = (const int*)d_in[0];
    const int*   ei  = (const int*)d_in[1];
    const float* emb = (const float*)d_in[3];
    int n = in_sizes[0];
    int E = in_sizes[1] / 2;
    const int* src = ei;
    const int* dst = ei + E;

    const float* Wl[3] = {(const float*)d_in[4], (const float*)d_in[8],  (const float*)d_in[12]};
    const float* bl[3] = {(const float*)d_in[5], (const float*)d_in[9],  (const float*)d_in[13]};
    const float* Wr[3] = {(const float*)d_in[6], (const float*)d_in[10], (const float*)d_in[14]};
    const float* ap[3] = {(const float*)d_in[7], (const float*)d_in[11], (const float*)d_in[15]};
    const float* Wout = (const float*)d_in[16];
    const float* bout = (const float*)d_in[17];

    // 1. CSR build
    zero_deg<<<(n + 255) / 256, 256>>>(n);
    count_deg<<<(E + 255) / 256, 256>>>(dst, E);
    scan_kernel<<<1, 1024>>>(n, E);
    fill_csr<<<(E + 255) / 256, 256>>>(src, dst, E);

    // 2. h0 = emb[x] -> buf 0
    gather_emb<<<(n * DV4 + 255) / 256, 256>>>(x, emb, n);

    // 3. three SAGE layers
    dim3 ggrid((n + 63) / 64, D / 64);
    int h = 0, o = 1;
    for (int l = 0; l < 3; l++) {
        aggregate<<<((size_t)n * 32 + 255) / 256, 256>>>(h, n);
        gemm_fused<true, true><<<ggrid, 256>>>(
            2 /*g_agg*/, h, Wl[l], Wr[l], bl[l], ap[l], nullptr, o, n);
        int t = h; h = o; o = t;
    }

    // 4. output projection -> d_out
    gemm_fused<false, false><<<ggrid, 256>>>(
        h, 0, Wout, nullptr, bout, nullptr, (float*)d_out, -1, n);
}

// round 8
// speedup vs baseline: 1.8292x; 1.8292x over previous
#include <cuda_runtime.h>
#include <cuda_bf16.h>
#include <cstdint>

// ---------------------------------------------------------------------------
// GraphSAGE on GB300 (built for base sm_103: no tcgen05) —
// bf16-split mma.sync GEMM + CSR mean aggregation.
//
//   h, agg kept as bf16 hi/lo plane pairs (hi+lo ~= fp32, err ~2^-18).
//   GEMM: mma.sync.m16n8k16 bf16, fp32 accum, 3-product split
//         (hi*hi + hi*lo + lo*hi), dual operand fused as K-chunk loop.
// ---------------------------------------------------------------------------

#define NMAX 100032
#define EMAX 3200000
#define D    256

// ---- static device scratch (no runtime allocation) ----
__device__ __align__(16) __nv_bfloat16 g_hiP[3][(size_t)NMAX * D];  // 0,1 = h ping-pong, 2 = agg
__device__ __align__(16) __nv_bfloat16 g_loP[3][(size_t)NMAX * D];
__device__ __align__(16) unsigned g_Whi[7 * 32768];   // 7 weight mats as bf16x2
__device__ __align__(16) unsigned g_Wlo[7 * 32768];
__device__ int   g_deg[NMAX];
__device__ int   g_rowptr[NMAX + 1];
__device__ int   g_cursor[NMAX];
__device__ float g_inv[NMAX];
__device__ int   g_col[EMAX];

// ---------------------------------------------------------------------------
// helpers
// ---------------------------------------------------------------------------
__device__ __forceinline__ uint32_t smem_to_u32(const void* p) {
    uint32_t a;
    asm("{ .reg .u64 t; cvta.to.shared.u64 t, %1; cvt.u32.u64 %0, t; }"
        : "=r"(a) : "l"(p));
    return a;
}

__device__ __forceinline__ void ldsm4(uint32_t addr, uint32_t& r0, uint32_t& r1,
                                      uint32_t& r2, uint32_t& r3) {
    asm volatile("ldmatrix.sync.aligned.m8n8.x4.shared.b16 {%0,%1,%2,%3}, [%4];"
                 : "=r"(r0), "=r"(r1), "=r"(r2), "=r"(r3) : "r"(addr));
}

__device__ __forceinline__ void mma16816(float* c, uint32_t a0, uint32_t a1,
                                         uint32_t a2, uint32_t a3,
                                         uint32_t b0, uint32_t b1) {
    asm volatile(
        "mma.sync.aligned.m16n8k16.row.col.f32.bf16.bf16.f32 "
        "{%0,%1,%2,%3}, {%4,%5,%6,%7}, {%8,%9}, {%0,%1,%2,%3};"
        : "+f"(c[0]), "+f"(c[1]), "+f"(c[2]), "+f"(c[3])
        : "r"(a0), "r"(a1), "r"(a2), "r"(a3), "r"(b0), "r"(b1));
}

// split one fp32 pair into bf16x2 hi + bf16x2 lo
__device__ __forceinline__ void split2u(float a, float b, unsigned& hi, unsigned& lo) {
    __nv_bfloat162 h = __floats2bfloat162_rn(a, b);
    float2 hf = __bfloat1622float2(h);
    __nv_bfloat162 l = __floats2bfloat162_rn(a - hf.x, b - hf.y);
    hi = *reinterpret_cast<unsigned*>(&h);
    lo = *reinterpret_cast<unsigned*>(&l);
}

// ---------------------------------------------------------------------------
// CSR construction
// ---------------------------------------------------------------------------
__global__ void zero_deg(int n) {
    int i = blockIdx.x * blockDim.x + threadIdx.x;
    if (i < n) g_deg[i] = 0;
}

__global__ void count_deg(const int* __restrict__ dst, int E) {
    int i = blockIdx.x * blockDim.x + threadIdx.x;
    if (i < E) atomicAdd(&g_deg[dst[i]], 1);
}

__global__ void scan_kernel(int n, int E) {
    __shared__ int sums[1024];
    int t = threadIdx.x;
    int chunk = (n + 1023) >> 10;
    int b = t * chunk;
    int e = min(b + chunk, n);
    int s = 0;
    for (int i = b; i < e; i++) s += g_deg[i];
    sums[t] = s;
    __syncthreads();
    for (int off = 1; off < 1024; off <<= 1) {
        int v = (t >= off) ? sums[t - off] : 0;
        __syncthreads();
        sums[t] += v;
        __syncthreads();
    }
    int prefix = (t == 0) ? 0 : sums[t - 1];
    for (int i = b; i < e; i++) {
        int d = g_deg[i];
        g_rowptr[i] = prefix;
        g_cursor[i] = prefix;
        g_inv[i]    = 1.0f / (float)max(d, 1);
        prefix += d;
    }
    if (t == 0) g_rowptr[n] = E;
}

__global__ void fill_csr(const int* __restrict__ src,
                         const int* __restrict__ dst, int E) {
    int i = blockIdx.x * blockDim.x + threadIdx.x;
    if (i < E) {
        int d = dst[i];
        int p = atomicAdd(&g_cursor[d], 1);
        g_col[p] = src[i];
    }
}

// ---------------------------------------------------------------------------
// Weight conversion: 7 fp32 [256,256] matrices -> bf16 hi/lo planes
// ---------------------------------------------------------------------------
struct WPtrs { const float* p[7]; };

__global__ void convert_w(WPtrs wp) {
    int i = blockIdx.x * blockDim.x + threadIdx.x;
    if (i >= 7 * 32768) return;
    int w = i >> 15;
    int e = (i & 32767) * 2;
    const float* src = wp.p[w];
    unsigned hi, lo;
    split2u(__ldg(&src[e]), __ldg(&src[e + 1]), hi, lo);
    g_Whi[i] = hi;
    g_Wlo[i] = lo;
}

// ---------------------------------------------------------------------------
// h0 = emb[x] -> hi/lo planes of buffer 0
// ---------------------------------------------------------------------------
__global__ void gather_emb(const int* __restrict__ x,
                           const float* __restrict__ emb, int n) {
    int i = blockIdx.x * blockDim.x + threadIdx.x;
    if (i >= n * 32) return;
    int node = i >> 5, q = i & 31;
    const float4* src = (const float4*)(emb + (size_t)__ldg(&x[node]) * D) + q * 2;
    float4 f0 = __ldg(src), f1 = __ldg(src + 1);
    unsigned h0, l0, h1, l1, h2, l2, h3, l3;
    split2u(f0.x, f0.y, h0, l0); split2u(f0.z, f0.w, h1, l1);
    split2u(f1.x, f1.y, h2, l2); split2u(f1.z, f1.w, h3, l3);
    ((uint4*)g_hiP[0])[(size_t)node * 32 + q] = make_uint4(h0, h1, h2, h3);
    ((uint4*)g_loP[0])[(size_t)node * 32 + q] = make_uint4(l0, l1, l2, l3);
}

// ---------------------------------------------------------------------------
// Mean aggregation: warp per node, fp32 register accum, reads hi+lo planes.
// ---------------------------------------------------------------------------
__global__ void __launch_bounds__(256)
aggregate(int selH, int n) {
    int w = (blockIdx.x * blockDim.x + threadIdx.x) >> 5;
    if (w >= n) return;
    int lane = threadIdx.x & 31;
    const uint4* hv = (const uint4*)g_hiP[selH];
    const uint4* lv = (const uint4*)g_loP[selH];
    int s = g_rowptr[w], e = g_rowptr[w + 1];
    float acc[8] = {0.f, 0.f, 0.f, 0.f, 0.f, 0.f, 0.f, 0.f};
    for (int t = s; t < e; t++) {
        size_t j = (size_t)__ldg(&g_col[t]) * 32 + lane;
        uint4 h4 = __ldg(&hv[j]);
        uint4 l4 = __ldg(&lv[j]);
        const unsigned* hp = (const unsigned*)&h4;
        const unsigned* lp = (const unsigned*)&l4;
#pragma unroll
        for (int p = 0; p < 4; p++) {
            float2 fh = __bfloat1622float2(*(const __nv_bfloat162*)&hp[p]);
            float2 fl = __bfloat1622float2(*(const __nv_bfloat162*)&lp[p]);
            acc[p * 2]     += fh.x + fl.x;
            acc[p * 2 + 1] += fh.y + fl.y;
        }
    }
    float iv = g_inv[w];
    unsigned ho[4], lo[4];
#pragma unroll
    for (int p = 0; p < 4; p++)
        split2u(acc[p * 2] * iv, acc[p * 2 + 1] * iv, ho[p], lo[p]);
    ((uint4*)g_hiP[2])[(size_t)w * 32 + lane] = make_uint4(ho[0], ho[1], ho[2], ho[3]);
    ((uint4*)g_loP[2])[(size_t)w * 32 + lane] = make_uint4(lo[0], lo[1], lo[2], lo[3]);
}

// ---------------------------------------------------------------------------
// mma.sync bf16-split GEMM.
//   LAYER=true : C = agg@Wl^T + h@Wr^T + bias, PReLU, write hi/lo planes.
//   LAYER=false: C = h@Wout^T + bias, write fp32 to Cext.
// Block: 256 thr = 8 warps (4M x 2N), tile M=128 N=64, K chunks of 64.
// Smem rows are 128B with 16B-granularity XOR swizzle (conflict-free LDSM).
// ---------------------------------------------------------------------------
static constexpr int SM_AHI = 0;
static constexpr int SM_ALO = 16384;
static constexpr int SM_WHI = 32768;
static constexpr int SM_WLO = 40960;
static constexpr int SMEM_TOTAL = 49152;

template <bool LAYER>
__global__ void __launch_bounds__(256)
gemm_mma(int selA2, int selOut, int ws1, int ws2,
         const float* __restrict__ bias, const float* __restrict__ slope,
         float* __restrict__ Cext, int n) {
    extern __shared__ __align__(16) char smem[];
    uint32_t sb = smem_to_u32(smem);
    int tid = threadIdx.x, wid = tid >> 5, lane = tid & 31;
    int warpM = wid & 3, warpN = wid >> 2;
    int m0 = blockIdx.x * 128, o0 = blockIdx.y * 64;

    float acc[2][4][4];
#pragma unroll
    for (int a = 0; a < 2; a++)
#pragma unroll
        for (int b = 0; b < 4; b++)
#pragma unroll
            for (int c = 0; c < 4; c++) acc[a][b][c] = 0.f;

    // ldmatrix lane addressing (constant per thread)
    int aRow = warpM * 32 + (lane & 15);
    int bRow = warpN * 32 + (lane & 15);
    int kbL  = (lane >> 4) * 16;          // 0 or 16 bytes (k half)
    uint32_t aXor = (uint32_t)((aRow & 7) << 4);
    uint32_t bXor = (uint32_t)((bRow & 7) << 4);

    const int NC = LAYER ? 8 : 4;
    for (int c = 0; c < NC; c++) {
        int op = LAYER ? (c >> 2) : 0;
        int kk = (c & 3) * 64;
        const __nv_bfloat16* Ah;
        const __nv_bfloat16* Al;
        if (LAYER && op == 0) { Ah = g_hiP[2];     Al = g_loP[2]; }
        else                  { Ah = g_hiP[selA2]; Al = g_loP[selA2]; }
        int ws = op ? ws2 : ws1;
        const __nv_bfloat16* Wh = (const __nv_bfloat16*)g_Whi + (size_t)ws * 65536;
        const __nv_bfloat16* Wl = (const __nv_bfloat16*)g_Wlo + (size_t)ws * 65536;

        __syncthreads();   // all warps done reading previous chunk's tiles
        // A tiles: 128 rows x 64 cols (128B/row) per plane
#pragma unroll
        for (int v = tid; v < 1024; v += 256) {
            int row = v >> 3, j = v & 7;
            int gr = min(m0 + row, n - 1);
            uint32_t so = (uint32_t)(row * 128 + ((j * 16) ^ ((row & 7) << 4)));
            size_t goff = (size_t)gr * D + kk + j * 8;
            *(uint4*)(smem + SM_AHI + so) = __ldg((const uint4*)(Ah + goff));
            *(uint4*)(smem + SM_ALO + so) = __ldg((const uint4*)(Al + goff));
        }
        // W tiles: 64 rows x 64 cols per plane
#pragma unroll
        for (int v = tid; v < 512; v += 256) {
            int row = v >> 3, j = v & 7;
            uint32_t so = (uint32_t)(row * 128 + ((j * 16) ^ ((row & 7) << 4)));
            size_t goff = (size_t)(o0 + row) * D + kk + j * 8;
            *(uint4*)(smem + SM_WHI + so) = __ldg((const uint4*)(Wh + goff));
            *(uint4*)(smem + SM_WLO + so) = __ldg((const uint4*)(Wl + goff));
        }
        __syncthreads();

        // 3 split products: (Ahi,Whi), (Ahi,Wlo), (Alo,Whi)
#pragma unroll
        for (int p = 0; p < 3; p++) {
            uint32_t aB = sb + (p == 2 ? SM_ALO : SM_AHI);
            uint32_t wB = sb + (p == 1 ? SM_WLO : SM_WHI);
#pragma unroll
            for (int k = 0; k < 4; k++) {
                uint32_t kb = (uint32_t)(k * 32 + kbL);
                uint32_t af[2][4], bf[2][4];
#pragma unroll
                for (int mt = 0; mt < 2; mt++)
                    ldsm4(aB + (uint32_t)((aRow + mt * 16) * 128) + (kb ^ aXor),
                          af[mt][0], af[mt][1], af[mt][2], af[mt][3]);
#pragma unroll
                for (int nt2 = 0; nt2 < 2; nt2++)
                    ldsm4(wB + (uint32_t)((bRow + nt2 * 16) * 128) + (kb ^ bXor),
                          bf[nt2][0], bf[nt2][1], bf[nt2][2], bf[nt2][3]);
#pragma unroll
                for (int mt = 0; mt < 2; mt++)
#pragma unroll
                    for (int nt2 = 0; nt2 < 2; nt2++) {
                        mma16816(acc[mt][nt2 * 2],
                                 af[mt][0], af[mt][1], af[mt][2], af[mt][3],
                                 bf[nt2][0], bf[nt2][2]);
                        mma16816(acc[mt][nt2 * 2 + 1],
                                 af[mt][0], af[mt][1], af[mt][2], af[mt][3],
                                 bf[nt2][1], bf[nt2][3]);
                    }
            }
        }
    }

    // ---- epilogue: direct stores from mma fragments ----
    int quad = lane >> 2, qt = lane & 3;
    float sl = LAYER ? __ldg(slope) : 0.f;
    float bj0[4], bj1[4];
#pragma unroll
    for (int nt = 0; nt < 4; nt++) {
        int col = o0 + warpN * 32 + nt * 8 + qt * 2;
        bj0[nt] = __ldg(&bias[col]);
        bj1[nt] = __ldg(&bias[col + 1]);
    }
#pragma unroll
    for (int mt = 0; mt < 2; mt++) {
#pragma unroll
        for (int half = 0; half < 2; half++) {
            int gr = m0 + warpM * 32 + mt * 16 + quad + half * 8;
            if (gr < n) {
#pragma unroll
                for (int nt = 0; nt < 4; nt++) {
                    float v0 = acc[mt][nt][half * 2]     + bj0[nt];
                    float v1 = acc[mt][nt][half * 2 + 1] + bj1[nt];
                    int cp = (o0 >> 1) + warpN * 16 + nt * 4 + qt;  // col pair idx
                    if (LAYER) {
                        v0 = (v0 >= 0.f) ? v0 : sl * v0;
                        v1 = (v1 >= 0.f) ? v1 : sl * v1;
                        unsigned hi, lo;
                        split2u(v0, v1, hi, lo);
                        size_t idx = (size_t)gr * 128 + cp;
                        ((unsigned*)g_hiP[selOut])[idx] = hi;
                        ((unsigned*)g_loP[selOut])[idx] = lo;
                    } else {
                        ((float2*)Cext)[(size_t)gr * 128 + cp] = make_float2(v0, v1);
                    }
                }
            }
        }
    }
}

// ---------------------------------------------------------------------------
// Host launcher
// Inputs: 0 x(i32,N) 1 edge_index(i32,2E) 2 edge_weight(unused) 3 emb
//         4 Wl1 5 bl1 6 Wr1 7 a1  8 Wl2 9 bl2 10 Wr2 11 a2
//         12 Wl3 13 bl3 14 Wr3 15 a3  16 Wout 17 bout
// ---------------------------------------------------------------------------
extern "C" void kernel_launch(void* const* d_in, const int* in_sizes, int n_in,
                              void* d_out, int out_size) {
    const int*   x   = (const int*)d_in[0];
    const int*   ei  = (const int*)d_in[1];
    const float* emb = (const float*)d_in[3];
    int n = in_sizes[0];
    int E = in_sizes[1] / 2;
    const int* src = ei;
    const int* dst = ei + E;

    const float* bl[3] = {(const float*)d_in[5], (const float*)d_in[9],  (const float*)d_in[13]};
    const float* ap[3] = {(const float*)d_in[7], (const float*)d_in[11], (const float*)d_in[15]};
    const float* bout  = (const float*)d_in[17];

    cudaFuncSetAttribute(gemm_mma<true>,  cudaFuncAttributeMaxDynamicSharedMemorySize, SMEM_TOTAL);
    cudaFuncSetAttribute(gemm_mma<false>, cudaFuncAttributeMaxDynamicSharedMemorySize, SMEM_TOTAL);

    // weight slots: 0..2 = Wl1..3, 3..5 = Wr1..3, 6 = Wout
    WPtrs wp;
    wp.p[0] = (const float*)d_in[4];
    wp.p[1] = (const float*)d_in[8];
    wp.p[2] = (const float*)d_in[12];
    wp.p[3] = (const float*)d_in[6];
    wp.p[4] = (const float*)d_in[10];
    wp.p[5] = (const float*)d_in[14];
    wp.p[6] = (const float*)d_in[16];
    convert_w<<<896, 256>>>(wp);

    // CSR build
    zero_deg<<<(n + 255) / 256, 256>>>(n);
    count_deg<<<(E + 255) / 256, 256>>>(dst, E);
    scan_kernel<<<1, 1024>>>(n, E);
    fill_csr<<<(E + 255) / 256, 256>>>(src, dst, E);

    // h0 = emb[x] -> planes 0
    gather_emb<<<(n * 32 + 255) / 256, 256>>>(x, emb, n);

    dim3 gg((n + 127) / 128, 4);
    int h = 0, o = 1;
    for (int l = 0; l < 3; l++) {
        aggregate<<<((size_t)n * 32 + 255) / 256, 256>>>(h, n);
        gemm_mma<true><<<gg, 256, SMEM_TOTAL>>>(h, o, l, 3 + l, bl[l], ap[l], nullptr, n);
        int t = h; h = o; o = t;
    }
    gemm_mma<false><<<gg, 256, SMEM_TOTAL>>>(h, 0, 6, 0, bout, nullptr, (float*)d_out, n);
}

// round 9
// speedup vs baseline: 2.0467x; 1.1189x over previous
#include <cuda_runtime.h>
#include <cuda_bf16.h>
#include <cstdint>

// ---------------------------------------------------------------------------
// GraphSAGE on GB300 (built for base sm_103: no tcgen05) —
// bf16-split mma.sync GEMM + CSR mean aggregation.
//
//   h, agg kept as bf16 hi/lo plane pairs (hi+lo ~= fp32, err ~2^-18).
//   GEMM: mma.sync.m16n8k16 bf16, fp32 accum, 3-product split
//         (hi*hi + hi*lo + lo*hi), dual operand fused as K-chunk loop.
//   R8 change: monolithic single-block scan (218us, serialized the chip)
//   replaced by 3-kernel parallel scan (~10us).
// ---------------------------------------------------------------------------

#define NMAX 100032
#define EMAX 3200000
#define D    256

// ---- static device scratch (no runtime allocation) ----
__device__ __align__(16) __nv_bfloat16 g_hiP[3][(size_t)NMAX * D];  // 0,1 = h ping-pong, 2 = agg
__device__ __align__(16) __nv_bfloat16 g_loP[3][(size_t)NMAX * D];
__device__ __align__(16) unsigned g_Whi[7 * 32768];   // 7 weight mats as bf16x2
__device__ __align__(16) unsigned g_Wlo[7 * 32768];
__device__ int   g_deg[NMAX];
__device__ int   g_rowptr[NMAX + 1];
__device__ int   g_cursor[NMAX];
__device__ float g_inv[NMAX];
__device__ int   g_col[EMAX];
__device__ int   g_bsum[1024];
__device__ int   g_boff[1024];

// ---------------------------------------------------------------------------
// helpers
// ---------------------------------------------------------------------------
__device__ __forceinline__ uint32_t smem_to_u32(const void* p) {
    uint32_t a;
    asm("{ .reg .u64 t; cvta.to.shared.u64 t, %1; cvt.u32.u64 %0, t; }"
        : "=r"(a) : "l"(p));
    return a;
}

__device__ __forceinline__ void ldsm4(uint32_t addr, uint32_t& r0, uint32_t& r1,
                                      uint32_t& r2, uint32_t& r3) {
    asm volatile("ldmatrix.sync.aligned.m8n8.x4.shared.b16 {%0,%1,%2,%3}, [%4];"
                 : "=r"(r0), "=r"(r1), "=r"(r2), "=r"(r3) : "r"(addr));
}

__device__ __forceinline__ void mma16816(float* c, uint32_t a0, uint32_t a1,
                                         uint32_t a2, uint32_t a3,
                                         uint32_t b0, uint32_t b1) {
    asm volatile(
        "mma.sync.aligned.m16n8k16.row.col.f32.bf16.bf16.f32 "
        "{%0,%1,%2,%3}, {%4,%5,%6,%7}, {%8,%9}, {%0,%1,%2,%3};"
        : "+f"(c[0]), "+f"(c[1]), "+f"(c[2]), "+f"(c[3])
        : "r"(a0), "r"(a1), "r"(a2), "r"(a3), "r"(b0), "r"(b1));
}

// split one fp32 pair into bf16x2 hi + bf16x2 lo
__device__ __forceinline__ void split2u(float a, float b, unsigned& hi, unsigned& lo) {
    __nv_bfloat162 h = __floats2bfloat162_rn(a, b);
    float2 hf = __bfloat1622float2(h);
    __nv_bfloat162 l = __floats2bfloat162_rn(a - hf.x, b - hf.y);
    hi = *reinterpret_cast<unsigned*>(&h);
    lo = *reinterpret_cast<unsigned*>(&l);
}

// ---------------------------------------------------------------------------
// CSR construction
// ---------------------------------------------------------------------------
__global__ void zero_deg(int n) {
    int i = blockIdx.x * blockDim.x + threadIdx.x;
    if (i < n) g_deg[i] = 0;
}

__global__ void count_deg(const int* __restrict__ dst, int E) {
    int i = blockIdx.x * blockDim.x + threadIdx.x;
    if (i < E) atomicAdd(&g_deg[dst[i]], 1);
}

// Phase 1: per-block (256-wide) sums of g_deg
__global__ void block_sums(int n) {
    int i = blockIdx.x * 256 + threadIdx.x;
    int v = (i < n) ? g_deg[i] : 0;
#pragma unroll
    for (int off = 16; off > 0; off >>= 1)
        v += __shfl_down_sync(0xFFFFFFFF, v, off);
    __shared__ int ws[8];
    int lane = threadIdx.x & 31, warp = threadIdx.x >> 5;
    if (lane == 0) ws[warp] = v;
    __syncthreads();
    if (threadIdx.x == 0) {
        int s = 0;
#pragma unroll
        for (int w = 0; w < 8; w++) s += ws[w];
        g_bsum[blockIdx.x] = s;
    }
}

// Phase 2: one block scans up to 1024 block sums -> exclusive offsets
__global__ void scan_bsums(int nb, int n, int E) {
    __shared__ int s[1024];
    int t = threadIdx.x;
    int v = (t < nb) ? g_bsum[t] : 0;
    s[t] = v;
    __syncthreads();
    for (int off = 1; off < 1024; off <<= 1) {
        int u = (t >= off) ? s[t - off] : 0;
        __syncthreads();
        s[t] += u;
        __syncthreads();
    }
    g_boff[t] = s[t] - v;   // exclusive
    if (t == 0) g_rowptr[n] = E;
}

// Phase 3: block-local exclusive scan + block offset -> rowptr/cursor/inv
__global__ void fill_row(int n) {
    int i = blockIdx.x * 256 + threadIdx.x;
    int lane = threadIdx.x & 31, warp = threadIdx.x >> 5;
    int d = (i < n) ? g_deg[i] : 0;
    // warp inclusive scan
    int inc = d;
#pragma unroll
    for (int off = 1; off < 32; off <<= 1) {
        int u = __shfl_up_sync(0xFFFFFFFF, inc, off);
        if (lane >= off) inc += u;
    }
    __shared__ int wsum[8];
    if (lane == 31) wsum[warp] = inc;
    __syncthreads();
    int wbase = 0;
#pragma unroll
    for (int w = 0; w < 8; w++)
        if (w < warp) wbase += wsum[w];
    int ex = g_boff[blockIdx.x] + wbase + inc - d;
    if (i < n) {
        g_rowptr[i] = ex;
        g_cursor[i] = ex;
        g_inv[i]    = 1.0f / (float)max(d, 1);
    }
}

__global__ void fill_csr(const int* __restrict__ src,
                         const int* __restrict__ dst, int E) {
    int i = blockIdx.x * blockDim.x + threadIdx.x;
    if (i < E) {
        int d = dst[i];
        int p = atomicAdd(&g_cursor[d], 1);
        g_col[p] = src[i];
    }
}

// ---------------------------------------------------------------------------
// Weight conversion: 7 fp32 [256,256] matrices -> bf16 hi/lo planes
// ---------------------------------------------------------------------------
struct WPtrs { const float* p[7]; };

__global__ void convert_w(WPtrs wp) {
    int i = blockIdx.x * blockDim.x + threadIdx.x;
    if (i >= 7 * 32768) return;
    int w = i >> 15;
    int e = (i & 32767) * 2;
    const float* src = wp.p[w];
    unsigned hi, lo;
    split2u(__ldg(&src[e]), __ldg(&src[e + 1]), hi, lo);
    g_Whi[i] = hi;
    g_Wlo[i] = lo;
}

// ---------------------------------------------------------------------------
// h0 = emb[x] -> hi/lo planes of buffer 0
// ---------------------------------------------------------------------------
__global__ void gather_emb(const int* __restrict__ x,
                           const float* __restrict__ emb, int n) {
    int i = blockIdx.x * blockDim.x + threadIdx.x;
    if (i >= n * 32) return;
    int node = i >> 5, q = i & 31;
    const float4* src = (const float4*)(emb + (size_t)__ldg(&x[node]) * D) + q * 2;
    float4 f0 = __ldg(src), f1 = __ldg(src + 1);
    unsigned h0, l0, h1, l1, h2, l2, h3, l3;
    split2u(f0.x, f0.y, h0, l0); split2u(f0.z, f0.w, h1, l1);
    split2u(f1.x, f1.y, h2, l2); split2u(f1.z, f1.w, h3, l3);
    ((uint4*)g_hiP[0])[(size_t)node * 32 + q] = make_uint4(h0, h1, h2, h3);
    ((uint4*)g_loP[0])[(size_t)node * 32 + q] = make_uint4(l0, l1, l2, l3);
}

// ---------------------------------------------------------------------------
// Mean aggregation: warp per node, fp32 register accum, reads hi+lo planes.
// ---------------------------------------------------------------------------
__global__ void __launch_bounds__(256)
aggregate(int selH, int n) {
    int w = (blockIdx.x * blockDim.x + threadIdx.x) >> 5;
    if (w >= n) return;
    int lane = threadIdx.x & 31;
    const uint4* hv = (const uint4*)g_hiP[selH];
    const uint4* lv = (const uint4*)g_loP[selH];
    int s = g_rowptr[w], e = g_rowptr[w + 1];
    float acc[8] = {0.f, 0.f, 0.f, 0.f, 0.f, 0.f, 0.f, 0.f};
    for (int t = s; t < e; t++) {
        size_t j = (size_t)__ldg(&g_col[t]) * 32 + lane;
        uint4 h4 = __ldg(&hv[j]);
        uint4 l4 = __ldg(&lv[j]);
        const unsigned* hp = (const unsigned*)&h4;
        const unsigned* lp = (const unsigned*)&l4;
#pragma unroll
        for (int p = 0; p < 4; p++) {
            float2 fh = __bfloat1622float2(*(const __nv_bfloat162*)&hp[p]);
            float2 fl = __bfloat1622float2(*(const __nv_bfloat162*)&lp[p]);
            acc[p * 2]     += fh.x + fl.x;
            acc[p * 2 + 1] += fh.y + fl.y;
        }
    }
    float iv = g_inv[w];
    unsigned ho[4], lo[4];
#pragma unroll
    for (int p = 0; p < 4; p++)
        split2u(acc[p * 2] * iv, acc[p * 2 + 1] * iv, ho[p], lo[p]);
    ((uint4*)g_hiP[2])[(size_t)w * 32 + lane] = make_uint4(ho[0], ho[1], ho[2], ho[3]);
    ((uint4*)g_loP[2])[(size_t)w * 32 + lane] = make_uint4(lo[0], lo[1], lo[2], lo[3]);
}

// ---------------------------------------------------------------------------
// mma.sync bf16-split GEMM.
//   LAYER=true : C = agg@Wl^T + h@Wr^T + bias, PReLU, write hi/lo planes.
//   LAYER=false: C = h@Wout^T + bias, write fp32 to Cext.
// Block: 256 thr = 8 warps (4M x 2N), tile M=128 N=64, K chunks of 64.
// Smem rows are 128B with 16B-granularity XOR swizzle (conflict-free LDSM).
// ---------------------------------------------------------------------------
static constexpr int SM_AHI = 0;
static constexpr int SM_ALO = 16384;
static constexpr int SM_WHI = 32768;
static constexpr int SM_WLO = 40960;
static constexpr int SMEM_TOTAL = 49152;

template <bool LAYER>
__global__ void __launch_bounds__(256)
gemm_mma(int selA2, int selOut, int ws1, int ws2,
         const float* __restrict__ bias, const float* __restrict__ slope,
         float* __restrict__ Cext, int n) {
    extern __shared__ __align__(16) char smem[];
    uint32_t sb = smem_to_u32(smem);
    int tid = threadIdx.x, wid = tid >> 5, lane = tid & 31;
    int warpM = wid & 3, warpN = wid >> 2;
    int m0 = blockIdx.x * 128, o0 = blockIdx.y * 64;

    float acc[2][4][4];
#pragma unroll
    for (int a = 0; a < 2; a++)
#pragma unroll
        for (int b = 0; b < 4; b++)
#pragma unroll
            for (int c = 0; c < 4; c++) acc[a][b][c] = 0.f;

    // ldmatrix lane addressing (constant per thread)
    int aRow = warpM * 32 + (lane & 15);
    int bRow = warpN * 32 + (lane & 15);
    int kbL  = (lane >> 4) * 16;          // 0 or 16 bytes (k half)
    uint32_t aXor = (uint32_t)((aRow & 7) << 4);
    uint32_t bXor = (uint32_t)((bRow & 7) << 4);

    const int NC = LAYER ? 8 : 4;
    for (int c = 0; c < NC; c++) {
        int op = LAYER ? (c >> 2) : 0;
        int kk = (c & 3) * 64;
        const __nv_bfloat16* Ah;
        const __nv_bfloat16* Al;
        if (LAYER && op == 0) { Ah = g_hiP[2];     Al = g_loP[2]; }
        else                  { Ah = g_hiP[selA2]; Al = g_loP[selA2]; }
        int ws = op ? ws2 : ws1;
        const __nv_bfloat16* Wh = (const __nv_bfloat16*)g_Whi + (size_t)ws * 65536;
        const __nv_bfloat16* Wl = (const __nv_bfloat16*)g_Wlo + (size_t)ws * 65536;

        __syncthreads();   // all warps done reading previous chunk's tiles
        // A tiles: 128 rows x 64 cols (128B/row) per plane
#pragma unroll
        for (int v = tid; v < 1024; v += 256) {
            int row = v >> 3, j = v & 7;
            int gr = min(m0 + row, n - 1);
            uint32_t so = (uint32_t)(row * 128 + ((j * 16) ^ ((row & 7) << 4)));
            size_t goff = (size_t)gr * D + kk + j * 8;
            *(uint4*)(smem + SM_AHI + so) = __ldg((const uint4*)(Ah + goff));
            *(uint4*)(smem + SM_ALO + so) = __ldg((const uint4*)(Al + goff));
        }
        // W tiles: 64 rows x 64 cols per plane
#pragma unroll
        for (int v = tid; v < 512; v += 256) {
            int row = v >> 3, j = v & 7;
            uint32_t so = (uint32_t)(row * 128 + ((j * 16) ^ ((row & 7) << 4)));
            size_t goff = (size_t)(o0 + row) * D + kk + j * 8;
            *(uint4*)(smem + SM_WHI + so) = __ldg((const uint4*)(Wh + goff));
            *(uint4*)(smem + SM_WLO + so) = __ldg((const uint4*)(Wl + goff));
        }
        __syncthreads();

        // 3 split products: (Ahi,Whi), (Ahi,Wlo), (Alo,Whi)
#pragma unroll
        for (int p = 0; p < 3; p++) {
            uint32_t aB = sb + (p == 2 ? SM_ALO : SM_AHI);
            uint32_t wB = sb + (p == 1 ? SM_WLO : SM_WHI);
#pragma unroll
            for (int k = 0; k < 4; k++) {
                uint32_t kb = (uint32_t)(k * 32 + kbL);
                uint32_t af[2][4], bf[2][4];
#pragma unroll
                for (int mt = 0; mt < 2; mt++)
                    ldsm4(aB + (uint32_t)((aRow + mt * 16) * 128) + (kb ^ aXor),
                          af[mt][0], af[mt][1], af[mt][2], af[mt][3]);
#pragma unroll
                for (int nt2 = 0; nt2 < 2; nt2++)
                    ldsm4(wB + (uint32_t)((bRow + nt2 * 16) * 128) + (kb ^ bXor),
                          bf[nt2][0], bf[nt2][1], bf[nt2][2], bf[nt2][3]);
#pragma unroll
                for (int mt = 0; mt < 2; mt++)
#pragma unroll
                    for (int nt2 = 0; nt2 < 2; nt2++) {
                        mma16816(acc[mt][nt2 * 2],
                                 af[mt][0], af[mt][1], af[mt][2], af[mt][3],
                                 bf[nt2][0], bf[nt2][2]);
                        mma16816(acc[mt][nt2 * 2 + 1],
                                 af[mt][0], af[mt][1], af[mt][2], af[mt][3],
                                 bf[nt2][1], bf[nt2][3]);
                    }
            }
        }
    }

    // ---- epilogue: direct stores from mma fragments ----
    int quad = lane >> 2, qt = lane & 3;
    float sl = LAYER ? __ldg(slope) : 0.f;
    float bj0[4], bj1[4];
#pragma unroll
    for (int nt = 0; nt < 4; nt++) {
        int col = o0 + warpN * 32 + nt * 8 + qt * 2;
        bj0[nt] = __ldg(&bias[col]);
        bj1[nt] = __ldg(&bias[col + 1]);
    }
#pragma unroll
    for (int mt = 0; mt < 2; mt++) {
#pragma unroll
        for (int half = 0; half < 2; half++) {
            int gr = m0 + warpM * 32 + mt * 16 + quad + half * 8;
            if (gr < n) {
#pragma unroll
                for (int nt = 0; nt < 4; nt++) {
                    float v0 = acc[mt][nt][half * 2]     + bj0[nt];
                    float v1 = acc[mt][nt][half * 2 + 1] + bj1[nt];
                    int cp = (o0 >> 1) + warpN * 16 + nt * 4 + qt;  // col pair idx
                    if (LAYER) {
                        v0 = (v0 >= 0.f) ? v0 : sl * v0;
                        v1 = (v1 >= 0.f) ? v1 : sl * v1;
                        unsigned hi, lo;
                        split2u(v0, v1, hi, lo);
                        size_t idx = (size_t)gr * 128 + cp;
                        ((unsigned*)g_hiP[selOut])[idx] = hi;
                        ((unsigned*)g_loP[selOut])[idx] = lo;
                    } else {
                        ((float2*)Cext)[(size_t)gr * 128 + cp] = make_float2(v0, v1);
                    }
                }
            }
        }
    }
}

// ---------------------------------------------------------------------------
// Host launcher
// Inputs: 0 x(i32,N) 1 edge_index(i32,2E) 2 edge_weight(unused) 3 emb
//         4 Wl1 5 bl1 6 Wr1 7 a1  8 Wl2 9 bl2 10 Wr2 11 a2
//         12 Wl3 13 bl3 14 Wr3 15 a3  16 Wout 17 bout
// ---------------------------------------------------------------------------
extern "C" void kernel_launch(void* const* d_in, const int* in_sizes, int n_in,
                              void* d_out, int out_size) {
    const int*   x   = (const int*)d_in[0];
    const int*   ei  = (const int*)d_in[1];
    const float* emb = (const float*)d_in[3];
    int n = in_sizes[0];
    int E = in_sizes[1] / 2;
    const int* src = ei;
    const int* dst = ei + E;

    const float* bl[3] = {(const float*)d_in[5], (const float*)d_in[9],  (const float*)d_in[13]};
    const float* ap[3] = {(const float*)d_in[7], (const float*)d_in[11], (const float*)d_in[15]};
    const float* bout  = (const float*)d_in[17];

    cudaFuncSetAttribute(gemm_mma<true>,  cudaFuncAttributeMaxDynamicSharedMemorySize, SMEM_TOTAL);
    cudaFuncSetAttribute(gemm_mma<false>, cudaFuncAttributeMaxDynamicSharedMemorySize, SMEM_TOTAL);

    // weight slots: 0..2 = Wl1..3, 3..5 = Wr1..3, 6 = Wout
    WPtrs wp;
    wp.p[0] = (const float*)d_in[4];
    wp.p[1] = (const float*)d_in[8];
    wp.p[2] = (const float*)d_in[12];
    wp.p[3] = (const float*)d_in[6];
    wp.p[4] = (const float*)d_in[10];
    wp.p[5] = (const float*)d_in[14];
    wp.p[6] = (const float*)d_in[16];
    convert_w<<<896, 256>>>(wp);

    // CSR build (parallel 3-phase scan)
    int nb = (n + 255) / 256;
    zero_deg<<<nb, 256>>>(n);
    count_deg<<<(E + 255) / 256, 256>>>(dst, E);
    block_sums<<<nb, 256>>>(n);
    scan_bsums<<<1, 1024>>>(nb, n, E);
    fill_row<<<nb, 256>>>(n);
    fill_csr<<<(E + 255) / 256, 256>>>(src, dst, E);

    // h0 = emb[x] -> planes 0
    gather_emb<<<(n * 32 + 255) / 256, 256>>>(x, emb, n);

    dim3 gg((n + 127) / 128, 4);
    int h = 0, o = 1;
    for (int l = 0; l < 3; l++) {
        aggregate<<<((size_t)n * 32 + 255) / 256, 256>>>(h, n);
        gemm_mma<true><<<gg, 256, SMEM_TOTAL>>>(h, o, l, 3 + l, bl[l], ap[l], nullptr, n);
        int t = h; h = o; o = t;
    }
    gemm_mma<false><<<gg, 256, SMEM_TOTAL>>>(h, 0, 6, 0, bout, nullptr, (float*)d_out, n);
}